// round 5
// baseline (speedup 1.0000x reference)
#include <cuda_runtime.h>
#include <cstdint>

#define Bc 2
#define Sc 2048
#define Dc 1024
#define Hc 16
#define HDc 64
#define BHc (Bc*Hc)
#define SCALEc 0.125f            // 64^-0.5
#define KLOG2 0.1803368801111243f  // SCALEc * log2(e)

// ---- scratch (allocation-free rule: __device__ globals) --------------------
__device__ float g_Q[(size_t)Bc * Sc * Dc];
__device__ float g_K[(size_t)Bc * Sc * Dc];
__device__ float g_V[(size_t)Bc * Sc * Dc];
__device__ float g_ctx[(size_t)Bc * Sc * Dc];
__device__ float g_attn_fb[(size_t)BHc * Sc * Sc];   // fallback if out only holds `output`

// ---- helpers ----------------------------------------------------------------
__device__ __forceinline__ uint32_t f2tf(float x) {
    uint32_t r; asm("cvt.rna.tf32.f32 %0, %1;" : "=r"(r) : "f"(x)); return r;
}
__device__ __forceinline__ float ex2(float x) {
    float r; asm("ex2.approx.f32 %0, %1;" : "=f"(r) : "f"(x)); return r;
}
__device__ __forceinline__ void mma8(float* d, const uint32_t* a, const uint32_t* b) {
    asm volatile(
        "mma.sync.aligned.m16n8k8.row.col.f32.tf32.tf32.f32 "
        "{%0,%1,%2,%3}, {%4,%5,%6,%7}, {%8,%9}, {%0,%1,%2,%3};\n"
        : "+f"(d[0]), "+f"(d[1]), "+f"(d[2]), "+f"(d[3])
        : "r"(a[0]), "r"(a[1]), "r"(a[2]), "r"(a[3]), "r"(b[0]), "r"(b[1]));
}
__device__ __forceinline__ uint32_t smem_u32(const void* p) {
    uint32_t r;
    asm("{ .reg .u64 t; cvta.to.shared.u64 t, %1; cvt.u32.u64 %0, t; }"
        : "=r"(r) : "l"(p));
    return r;
}
__device__ __forceinline__ void cpa16(uint32_t saddr, const void* g) {
    asm volatile("cp.async.cg.shared.global [%0], [%1], 16;" :: "r"(saddr), "l"(g));
}
__device__ __forceinline__ void cpa_commit() { asm volatile("cp.async.commit_group;"); }
__device__ __forceinline__ void cpa_wait0()  { asm volatile("cp.async.wait_group 0;"); }

// ============================================================================
// GEMM + bias body (tf32 mma, double-buffered). Shared by out-proj and the
// merged QKV kernel. BM=BN=128, BK=16, 256 threads, warp tile 64x32.
// ============================================================================
struct GemmSmem {
    uint32_t As[2][16][136];
    uint32_t Bs[2][16][136];
};

__device__ __forceinline__
void gemm_body(const float* __restrict__ A, const float* __restrict__ W,
               const float* __restrict__ bias, float* __restrict__ C,
               int M, int N, int K, GemmSmem& sm) {
    const int tid = threadIdx.x;
    const int lane = tid & 31, warp = tid >> 5;
    const int wm = warp >> 2, wn = warp & 3;
    const int row0 = blockIdx.y * 128, col0 = blockIdx.x * 128;
    const int r_lo = lane >> 2, c_lo = lane & 3;

    const int fa0 = tid * 2, fa1 = tid * 2 + 1;
    const int ra0 = fa0 >> 2, ca0 = (fa0 & 3) * 4;
    const int ra1 = fa1 >> 2, ca1 = (fa1 & 3) * 4;
    const int rb0 = fa0 >> 5, cb0 = (fa0 & 31) * 4;
    const int rb1 = fa1 >> 5, cb1 = (fa1 & 31) * 4;

    float acc[4][4][4] = {};

    {
        float4 v;
        v = *reinterpret_cast<const float4*>(&A[(size_t)(row0 + ra0) * K + ca0]);
        sm.As[0][ca0+0][ra0]=f2tf(v.x); sm.As[0][ca0+1][ra0]=f2tf(v.y);
        sm.As[0][ca0+2][ra0]=f2tf(v.z); sm.As[0][ca0+3][ra0]=f2tf(v.w);
        v = *reinterpret_cast<const float4*>(&A[(size_t)(row0 + ra1) * K + ca1]);
        sm.As[0][ca1+0][ra1]=f2tf(v.x); sm.As[0][ca1+1][ra1]=f2tf(v.y);
        sm.As[0][ca1+2][ra1]=f2tf(v.z); sm.As[0][ca1+3][ra1]=f2tf(v.w);
        v = *reinterpret_cast<const float4*>(&W[(size_t)rb0 * N + col0 + cb0]);
        sm.Bs[0][rb0][cb0+0]=f2tf(v.x); sm.Bs[0][rb0][cb0+1]=f2tf(v.y);
        sm.Bs[0][rb0][cb0+2]=f2tf(v.z); sm.Bs[0][rb0][cb0+3]=f2tf(v.w);
        v = *reinterpret_cast<const float4*>(&W[(size_t)rb1 * N + col0 + cb1]);
        sm.Bs[0][rb1][cb1+0]=f2tf(v.x); sm.Bs[0][rb1][cb1+1]=f2tf(v.y);
        sm.Bs[0][rb1][cb1+2]=f2tf(v.z); sm.Bs[0][rb1][cb1+3]=f2tf(v.w);
    }
    __syncthreads();

    const int nk = K >> 4;
    float4 pa0, pa1, pb0, pb1;
    for (int kt = 0; kt < nk; kt++) {
        const int s = kt & 1;
        const int k0n = (kt + 1) << 4;
        if (kt + 1 < nk) {
            pa0 = *reinterpret_cast<const float4*>(&A[(size_t)(row0 + ra0) * K + k0n + ca0]);
            pa1 = *reinterpret_cast<const float4*>(&A[(size_t)(row0 + ra1) * K + k0n + ca1]);
            pb0 = *reinterpret_cast<const float4*>(&W[(size_t)(k0n + rb0) * N + col0 + cb0]);
            pb1 = *reinterpret_cast<const float4*>(&W[(size_t)(k0n + rb1) * N + col0 + cb1]);
        }
#pragma unroll
        for (int ks = 0; ks < 16; ks += 8) {
            uint32_t af[4][4], bf[4][2];
#pragma unroll
            for (int mt = 0; mt < 4; mt++) {
                int rb = wm * 64 + mt * 16 + r_lo;
                af[mt][0] = sm.As[s][ks + c_lo][rb];
                af[mt][1] = sm.As[s][ks + c_lo][rb + 8];
                af[mt][2] = sm.As[s][ks + 4 + c_lo][rb];
                af[mt][3] = sm.As[s][ks + 4 + c_lo][rb + 8];
            }
#pragma unroll
            for (int nt = 0; nt < 4; nt++) {
                int cb = wn * 32 + nt * 8 + r_lo;
                bf[nt][0] = sm.Bs[s][ks + c_lo][cb];
                bf[nt][1] = sm.Bs[s][ks + 4 + c_lo][cb];
            }
#pragma unroll
            for (int mt = 0; mt < 4; mt++)
#pragma unroll
                for (int nt = 0; nt < 4; nt++)
                    mma8(acc[mt][nt], af[mt], bf[nt]);
        }
        if (kt + 1 < nk) {
            const int d = s ^ 1;
            sm.As[d][ca0+0][ra0]=f2tf(pa0.x); sm.As[d][ca0+1][ra0]=f2tf(pa0.y);
            sm.As[d][ca0+2][ra0]=f2tf(pa0.z); sm.As[d][ca0+3][ra0]=f2tf(pa0.w);
            sm.As[d][ca1+0][ra1]=f2tf(pa1.x); sm.As[d][ca1+1][ra1]=f2tf(pa1.y);
            sm.As[d][ca1+2][ra1]=f2tf(pa1.z); sm.As[d][ca1+3][ra1]=f2tf(pa1.w);
            sm.Bs[d][rb0][cb0+0]=f2tf(pb0.x); sm.Bs[d][rb0][cb0+1]=f2tf(pb0.y);
            sm.Bs[d][rb0][cb0+2]=f2tf(pb0.z); sm.Bs[d][rb0][cb0+3]=f2tf(pb0.w);
            sm.Bs[d][rb1][cb1+0]=f2tf(pb1.x); sm.Bs[d][rb1][cb1+1]=f2tf(pb1.y);
            sm.Bs[d][rb1][cb1+2]=f2tf(pb1.z); sm.Bs[d][rb1][cb1+3]=f2tf(pb1.w);
        }
        __syncthreads();
    }

#pragma unroll
    for (int mt = 0; mt < 4; mt++) {
        int row = row0 + wm * 64 + mt * 16 + r_lo;
#pragma unroll
        for (int nt = 0; nt < 4; nt++) {
            int col = col0 + wn * 32 + nt * 8 + c_lo * 2;
            float b0 = bias[col], b1 = bias[col + 1];
            C[(size_t)row * N + col]           = acc[mt][nt][0] + b0;
            C[(size_t)row * N + col + 1]       = acc[mt][nt][1] + b1;
            C[(size_t)(row + 8) * N + col]     = acc[mt][nt][2] + b0;
            C[(size_t)(row + 8) * N + col + 1] = acc[mt][nt][3] + b1;
        }
    }
}

__global__ __launch_bounds__(256)
void gemm_bias_tc(const float* __restrict__ A, const float* __restrict__ W,
                  const float* __restrict__ bias, float* __restrict__ C,
                  int M, int N, int K) {
    __shared__ GemmSmem sm;
    gemm_body(A, W, bias, C, M, N, K, sm);
}

// merged QKV: blockIdx.z selects (input, weight, bias, dst)
__global__ __launch_bounds__(256)
void qkv_gemm(const float* __restrict__ q, const float* __restrict__ k,
              const float* __restrict__ v,
              const float* __restrict__ Wq, const float* __restrict__ bq,
              const float* __restrict__ Wk, const float* __restrict__ bk,
              const float* __restrict__ Wv, const float* __restrict__ bv,
              float* __restrict__ Qo, float* __restrict__ Ko, float* __restrict__ Vo) {
    __shared__ GemmSmem sm;
    const float *A, *W, *bias; float* C;
    if (blockIdx.z == 0)      { A = q; W = Wq; bias = bq; C = Qo; }
    else if (blockIdx.z == 1) { A = k; W = Wk; bias = bk; C = Ko; }
    else                      { A = v; W = Wv; bias = bv; C = Vo; }
    gemm_body(A, W, bias, C, Bc * Sc, Dc, Dc, sm);
}

// ============================================================================
// Fused attention: 512 threads (16 warps, 8m x 2n). Q in registers,
// K/V cp.async double-buffered, E regs->gmem (unnormalized), PV via shuffle
// transpose of S accumulators. Tail: in-block normalize of own E strip
// (L2-hot) + ctx write. No separate norm kernel, no inv gmem array.
// ============================================================================
#define FK0 0
#define FK1 8704
#define FV0 17408
#define FV1 26112
#define FRED 34816          // 256 floats: [row][wn]
#define FRED2 35072         // 128 floats: inv per row
#define FTOT 35200          // *4 = 140800 bytes

__global__ __launch_bounds__(512)
void fused_attn(const float* __restrict__ Qp, const float* __restrict__ Kp,
                const float* __restrict__ Vp, float* __restrict__ attn,
                float* __restrict__ ctx) {
    extern __shared__ float smf[];
    const uint32_t sbase = smem_u32(smf);

    const int bh = blockIdx.y, b = bh >> 4, h = bh & 15;
    const int row0 = blockIdx.x * 128;
    const float* Qh = Qp + (size_t)b * Sc * Dc + h * HDc;
    const float* Kh = Kp + (size_t)b * Sc * Dc + h * HDc;
    const float* Vh = Vp + (size_t)b * Sc * Dc + h * HDc;
    float* outp = attn + (size_t)bh * Sc * Sc;

    const int tid = threadIdx.x, lane = tid & 31, warp = tid >> 5;
    const int wm = warp >> 1, wn = warp & 1;   // 8m x 2n
    const int g = lane >> 2, c = lane & 3;

    const int ldr0 = tid >> 4;                 // rows 0..31 (+32 per i)
    const int ldc4 = (tid & 15) * 4;

    // ---- issue first K/V tile ----
    {
#pragma unroll
        for (int i = 0; i < 4; i++) {
            int r = ldr0 + i * 32;
            cpa16(sbase + (uint32_t)(FK0 + r * 68 + ldc4) * 4, Kh + (size_t)r * Dc + ldc4);
            cpa16(sbase + (uint32_t)(FV0 + r * 68 + ldc4) * 4, Vh + (size_t)r * Dc + ldc4);
        }
        cpa_commit();
    }

    // ---- Q fragments in registers ----
    uint32_t qf[8][4];
    {
        const int qr = row0 + wm * 16;
#pragma unroll
        for (int s8 = 0; s8 < 8; s8++) {
            qf[s8][0] = f2tf(Qh[(size_t)(qr + g)     * Dc + s8 * 8 + c]);
            qf[s8][1] = f2tf(Qh[(size_t)(qr + g + 8) * Dc + s8 * 8 + c]);
            qf[s8][2] = f2tf(Qh[(size_t)(qr + g)     * Dc + s8 * 8 + c + 4]);
            qf[s8][3] = f2tf(Qh[(size_t)(qr + g + 8) * Dc + s8 * 8 + c + 4]);
        }
    }

    cpa_wait0();
    __syncthreads();

    float accU[8][4] = {};
    float rs0 = 0.f, rs1 = 0.f;

    const int src1 = (lane & ~3) | (c >> 1);
    const int src2 = src1 + 2;
    const bool odd = (c & 1);

    for (int kt = 0; kt < 16; kt++) {
        const int s = kt & 1;
        if (kt + 1 < 16) {
            const float* gk = Kh + (size_t)((kt + 1) * 128) * Dc;
            const float* gv = Vh + (size_t)((kt + 1) * 128) * Dc;
            const int KD = s ? FK0 : FK1;
            const int VD = s ? FV0 : FV1;
#pragma unroll
            for (int i = 0; i < 4; i++) {
                int r = ldr0 + i * 32;
                cpa16(sbase + (uint32_t)(KD + r * 68 + ldc4) * 4, gk + (size_t)r * Dc + ldc4);
                cpa16(sbase + (uint32_t)(VD + r * 68 + ldc4) * 4, gv + (size_t)r * Dc + ldc4);
            }
            cpa_commit();
        }
        const float* sK = smf + (s ? FK1 : FK0);
        const float* sV = smf + (s ? FV1 : FV0);
        const int k0 = kt * 128;

#pragma unroll
        for (int half = 0; half < 2; half++) {
            const int colbase = wn * 64 + half * 32;

            float accS[4][4] = {};
#pragma unroll
            for (int s8 = 0; s8 < 8; s8++) {
                uint32_t bf[4][2];
#pragma unroll
                for (int nt = 0; nt < 4; nt++) {
                    int kc = colbase + nt * 8 + g;
                    bf[nt][0] = __float_as_uint(sK[kc * 68 + s8 * 8 + c]);
                    bf[nt][1] = __float_as_uint(sK[kc * 68 + s8 * 8 + c + 4]);
                }
#pragma unroll
                for (int nt = 0; nt < 4; nt++)
                    mma8(accS[nt], qf[s8], bf[nt]);
            }

            const int grow = row0 + wm * 16 + g;
#pragma unroll
            for (int nt = 0; nt < 4; nt++) {
                float e0 = ex2(accS[nt][0] * KLOG2);
                float e1 = ex2(accS[nt][1] * KLOG2);
                float e2 = ex2(accS[nt][2] * KLOG2);
                float e3 = ex2(accS[nt][3] * KLOG2);
                rs0 += e0 + e1; rs1 += e2 + e3;
                int gcol = k0 + colbase + nt * 8 + c * 2;
                *reinterpret_cast<float2*>(&outp[(size_t)grow * Sc + gcol])       = make_float2(e0, e1);
                *reinterpret_cast<float2*>(&outp[(size_t)(grow + 8) * Sc + gcol]) = make_float2(e2, e3);
                accS[nt][0] = e0; accS[nt][1] = e1; accS[nt][2] = e2; accS[nt][3] = e3;
            }

#pragma unroll
            for (int s4 = 0; s4 < 4; s4++) {
                float x0 = __shfl_sync(0xffffffffu, accS[s4][0], src1);
                float x1 = __shfl_sync(0xffffffffu, accS[s4][1], src1);
                float y0 = __shfl_sync(0xffffffffu, accS[s4][2], src1);
                float y1 = __shfl_sync(0xffffffffu, accS[s4][3], src1);
                float z0 = __shfl_sync(0xffffffffu, accS[s4][0], src2);
                float z1 = __shfl_sync(0xffffffffu, accS[s4][1], src2);
                float w0 = __shfl_sync(0xffffffffu, accS[s4][2], src2);
                float w1 = __shfl_sync(0xffffffffu, accS[s4][3], src2);
                uint32_t af[4];
                af[0] = f2tf(odd ? x1 : x0);
                af[1] = f2tf(odd ? y1 : y0);
                af[2] = f2tf(odd ? z1 : z0);
                af[3] = f2tf(odd ? w1 : w0);
                const int vr = colbase + s4 * 8 + c;
#pragma unroll
                for (int nt = 0; nt < 8; nt++) {
                    uint32_t bf[2];
                    bf[0] = __float_as_uint(sV[vr * 68 + nt * 8 + g]);
                    bf[1] = __float_as_uint(sV[(vr + 4) * 68 + nt * 8 + g]);
                    mma8(accU[nt], af, bf);
                }
            }
        }

        if (kt + 1 < 16) cpa_wait0();
        __syncthreads();
    }

    // ---- rowsum reduction -> inv (smem only) ----
    float* red  = smf + FRED;
    float* red2 = smf + FRED2;
    {
        float v0 = rs0, v1 = rs1;
        v0 += __shfl_xor_sync(0xffffffffu, v0, 1);
        v0 += __shfl_xor_sync(0xffffffffu, v0, 2);
        v1 += __shfl_xor_sync(0xffffffffu, v1, 1);
        v1 += __shfl_xor_sync(0xffffffffu, v1, 2);
        if (c == 0) {
            red[(wm * 16 + g) * 2 + wn]     = v0;
            red[(wm * 16 + g + 8) * 2 + wn] = v1;
        }
    }
    __syncthreads();
    if (tid < 128) {
        red2[tid] = 1.0f / (red[tid * 2] + red[tid * 2 + 1]);
    }
    __syncthreads();

    // ---- cross-warp U reduction (wn=1 -> smem, wn=0 adds + writes ctx) ----
    float* uRed = smf;   // reuse K0 region, stride 68
    if (wn == 1) {
#pragma unroll
        for (int nt = 0; nt < 8; nt++) {
            int rr = wm * 16 + g, cc = nt * 8 + c * 2;
            uRed[rr * 68 + cc]           = accU[nt][0];
            uRed[rr * 68 + cc + 1]       = accU[nt][1];
            uRed[(rr + 8) * 68 + cc]     = accU[nt][2];
            uRed[(rr + 8) * 68 + cc + 1] = accU[nt][3];
        }
    }
    __syncthreads();
    if (wn == 0) {
        float* cp = ctx + (size_t)(b * Sc + row0) * Dc + h * HDc;
        int rr = wm * 16 + g;
        float iv0 = red2[rr], iv1 = red2[rr + 8];
#pragma unroll
        for (int nt = 0; nt < 8; nt++) {
            int cc = nt * 8 + c * 2;
            float u0 = accU[nt][0] + uRed[rr * 68 + cc];
            float u1 = accU[nt][1] + uRed[rr * 68 + cc + 1];
            float u2 = accU[nt][2] + uRed[(rr + 8) * 68 + cc];
            float u3 = accU[nt][3] + uRed[(rr + 8) * 68 + cc + 1];
            cp[(size_t)rr * Dc + cc]           = u0 * iv0;
            cp[(size_t)rr * Dc + cc + 1]       = u1 * iv0;
            cp[(size_t)(rr + 8) * Dc + cc]     = u2 * iv1;
            cp[(size_t)(rr + 8) * Dc + cc + 1] = u3 * iv1;
        }
    }

    // ---- tail: normalize this block's own E strip (L2-hot) ----
    // rows row0..row0+127, 2048 cols = 65536 float4
    for (int idx = tid; idx < 128 * 512; idx += 512) {
        int r = idx >> 9;
        int c4 = (idx & 511) << 2;
        float iv = red2[r];
        float4* p = reinterpret_cast<float4*>(&outp[(size_t)(row0 + r) * Sc + c4]);
        float4 v = *p;
        v.x *= iv; v.y *= iv; v.z *= iv; v.w *= iv;
        *p = v;
    }
}

// ---------------------------------------------------------------------------
extern "C" void kernel_launch(void* const* d_in, const int* in_sizes, int n_in,
                              void* d_out, int out_size) {
    const float* query = (const float*)d_in[0];
    const float* key   = (const float*)d_in[1];
    const float* value = (const float*)d_in[2];
    const float* Wq = (const float*)d_in[3];
    const float* bq = (const float*)d_in[4];
    const float* Wk = (const float*)d_in[5];
    const float* bk = (const float*)d_in[6];
    const float* Wv = (const float*)d_in[7];
    const float* bv = (const float*)d_in[8];
    const float* Wo = (const float*)d_in[9];
    const float* bo = (const float*)d_in[10];

    float* out = (float*)d_out;
    const size_t OUT_E  = (size_t)Bc * Sc * Dc;
    const size_t ATTN_E = (size_t)BHc * Sc * Sc;

    float* attn;
    if ((size_t)out_size >= OUT_E + ATTN_E) {
        attn = out + OUT_E;
    } else {
        void* p = nullptr; cudaGetSymbolAddress(&p, g_attn_fb); attn = (float*)p;
    }
    float* Qp; { void* p; cudaGetSymbolAddress(&p, g_Q);   Qp = (float*)p; }
    float* Kp; { void* p; cudaGetSymbolAddress(&p, g_K);   Kp = (float*)p; }
    float* Vp; { void* p; cudaGetSymbolAddress(&p, g_V);   Vp = (float*)p; }
    float* Cx; { void* p; cudaGetSymbolAddress(&p, g_ctx); Cx = (float*)p; }

    cudaFuncSetAttribute(fused_attn, cudaFuncAttributeMaxDynamicSharedMemorySize,
                         FTOT * 4);

    const int M = Bc * Sc;                      // 4096
    dim3 thr(256);

    // merged QKV projections: one launch, 768 blocks
    qkv_gemm<<<dim3(Dc / 128, M / 128, 3), thr>>>(query, key, value,
                                                  Wq, bq, Wk, bk, Wv, bv,
                                                  Qp, Kp, Vp);

    dim3 gfa(Sc / 128, BHc);                    // (16, 32)
    fused_attn<<<gfa, dim3(512), FTOT * 4>>>(Qp, Kp, Vp, attn, Cx);

    gemm_bias_tc<<<dim3(Dc / 128, M / 128), thr>>>(Cx, Wo, bo, out, M, Dc, Dc);
}

// round 6
// speedup vs baseline: 1.1559x; 1.1559x over previous
#include <cuda_runtime.h>
#include <cstdint>

#define Bc 2
#define Sc 2048
#define Dc 1024
#define Hc 16
#define HDc 64
#define BHc (Bc*Hc)
#define SCALEc 0.125f              // 64^-0.5
#define KLOG2 0.1803368801111243f // SCALEc * log2(e)

// ---- scratch (allocation-free rule: __device__ globals) --------------------
__device__ float g_Q[(size_t)Bc * Sc * Dc];
__device__ float g_K[(size_t)Bc * Sc * Dc];
__device__ float g_V[(size_t)Bc * Sc * Dc];
__device__ float g_ctx[(size_t)Bc * Sc * Dc];
__device__ float g_invsum[(size_t)BHc * Sc];
__device__ float g_attn_fb[(size_t)BHc * Sc * Sc];   // fallback if out only holds `output`

// ---- helpers ----------------------------------------------------------------
__device__ __forceinline__ uint32_t f2tf(float x) {
    uint32_t r; asm("cvt.rna.tf32.f32 %0, %1;" : "=r"(r) : "f"(x)); return r;
}
__device__ __forceinline__ float ex2(float x) {
    float r; asm("ex2.approx.f32 %0, %1;" : "=f"(r) : "f"(x)); return r;
}
__device__ __forceinline__ void mma8(float* d, const uint32_t* a, const uint32_t* b) {
    asm volatile(
        "mma.sync.aligned.m16n8k8.row.col.f32.tf32.tf32.f32 "
        "{%0,%1,%2,%3}, {%4,%5,%6,%7}, {%8,%9}, {%0,%1,%2,%3};\n"
        : "+f"(d[0]), "+f"(d[1]), "+f"(d[2]), "+f"(d[3])
        : "r"(a[0]), "r"(a[1]), "r"(a[2]), "r"(a[3]), "r"(b[0]), "r"(b[1]));
}
__device__ __forceinline__ uint32_t smem_u32(const void* p) {
    uint32_t r;
    asm("{ .reg .u64 t; cvta.to.shared.u64 t, %1; cvt.u32.u64 %0, t; }"
        : "=r"(r) : "l"(p));
    return r;
}
__device__ __forceinline__ void cpa16(uint32_t saddr, const void* g) {
    asm volatile("cp.async.cg.shared.global [%0], [%1], 16;" :: "r"(saddr), "l"(g));
}
__device__ __forceinline__ void cpa_commit() { asm volatile("cp.async.commit_group;"); }
__device__ __forceinline__ void cpa_wait0()  { asm volatile("cp.async.wait_group 0;"); }
__device__ __forceinline__ void cpa_wait1()  { asm volatile("cp.async.wait_group 1;"); }

// ============================================================================
// GEMM + bias: cp.async double-buffered, raw-fp32-as-tf32 (no conversion).
// BM=BN=128, BK=16, 256 threads = 8 warps (2m x 4n), warp tile 64x32.
// ============================================================================
struct GemmSmem {
    float As[2][128][20];    // A tile, row-major, pad 20 (conflict-free frags)
    float Bs[2][16][136];    // W tile, row-major, pad 136
};

__device__ __forceinline__
void gemm_body(const float* __restrict__ A, const float* __restrict__ W,
               const float* __restrict__ bias, float* __restrict__ C,
               int M, int N, int K, GemmSmem& sm) {
    const int tid = threadIdx.x;
    const int lane = tid & 31, warp = tid >> 5;
    const int wm = warp >> 2, wn = warp & 3;
    const int row0 = blockIdx.y * 128, col0 = blockIdx.x * 128;
    const int r_lo = lane >> 2, c_lo = lane & 3;

    // staging coords: each thread cp.asyncs 2x16B of A and 2x16B of B
    const int rowA = tid >> 1, colA = (tid & 1) * 8;
    const int rowB = tid >> 4, colB = (tid & 15) * 8;

    const uint32_t sA[2] = { smem_u32(&sm.As[0][rowA][colA]),
                             smem_u32(&sm.As[1][rowA][colA]) };
    const uint32_t sB[2] = { smem_u32(&sm.Bs[0][rowB][colB]),
                             smem_u32(&sm.Bs[1][rowB][colB]) };
    const float* gA = A + (size_t)(row0 + rowA) * K + colA;
    const float* gB = W + (size_t)rowB * N + col0 + colB;

    float acc[4][4][4] = {};

    // prologue: stage 0
    cpa16(sA[0], gA); cpa16(sA[0] + 16, gA + 4);
    cpa16(sB[0], gB); cpa16(sB[0] + 16, gB + 4);
    cpa_commit();

    const int nk = K >> 4;
    for (int kt = 0; kt < nk; kt++) {
        const int s = kt & 1;
        if (kt + 1 < nk) {
            const float* gA2 = gA + (kt + 1) * 16;
            const float* gB2 = gB + (size_t)(kt + 1) * 16 * N;
            cpa16(sA[s ^ 1], gA2); cpa16(sA[s ^ 1] + 16, gA2 + 4);
            cpa16(sB[s ^ 1], gB2); cpa16(sB[s ^ 1] + 16, gB2 + 4);
            cpa_commit();
            cpa_wait1();
        } else {
            cpa_wait0();
        }
        __syncthreads();

        const float (*As_)[20]  = sm.As[s];
        const float (*Bs_)[136] = sm.Bs[s];
#pragma unroll
        for (int ks = 0; ks < 16; ks += 8) {
            uint32_t af[4][4], bf[4][2];
#pragma unroll
            for (int mt = 0; mt < 4; mt++) {
                int rb = wm * 64 + mt * 16 + r_lo;
                af[mt][0] = __float_as_uint(As_[rb][ks + c_lo]);
                af[mt][1] = __float_as_uint(As_[rb + 8][ks + c_lo]);
                af[mt][2] = __float_as_uint(As_[rb][ks + 4 + c_lo]);
                af[mt][3] = __float_as_uint(As_[rb + 8][ks + 4 + c_lo]);
            }
#pragma unroll
            for (int nt = 0; nt < 4; nt++) {
                int cb = wn * 32 + nt * 8 + r_lo;
                bf[nt][0] = __float_as_uint(Bs_[ks + c_lo][cb]);
                bf[nt][1] = __float_as_uint(Bs_[ks + 4 + c_lo][cb]);
            }
#pragma unroll
            for (int mt = 0; mt < 4; mt++)
#pragma unroll
                for (int nt = 0; nt < 4; nt++)
                    mma8(acc[mt][nt], af[mt], bf[nt]);
        }
        __syncthreads();
    }

#pragma unroll
    for (int mt = 0; mt < 4; mt++) {
        int row = row0 + wm * 64 + mt * 16 + r_lo;
#pragma unroll
        for (int nt = 0; nt < 4; nt++) {
            int col = col0 + wn * 32 + nt * 8 + c_lo * 2;
            float b0 = bias[col], b1 = bias[col + 1];
            C[(size_t)row * N + col]           = acc[mt][nt][0] + b0;
            C[(size_t)row * N + col + 1]       = acc[mt][nt][1] + b1;
            C[(size_t)(row + 8) * N + col]     = acc[mt][nt][2] + b0;
            C[(size_t)(row + 8) * N + col + 1] = acc[mt][nt][3] + b1;
        }
    }
}

__global__ __launch_bounds__(256)
void gemm_bias_tc(const float* __restrict__ A, const float* __restrict__ W,
                  const float* __restrict__ bias, float* __restrict__ C,
                  int M, int N, int K) {
    __shared__ GemmSmem sm;
    gemm_body(A, W, bias, C, M, N, K, sm);
}

__global__ __launch_bounds__(256)
void qkv_gemm(const float* __restrict__ q, const float* __restrict__ k,
              const float* __restrict__ v,
              const float* __restrict__ Wq, const float* __restrict__ bq,
              const float* __restrict__ Wk, const float* __restrict__ bk,
              const float* __restrict__ Wv, const float* __restrict__ bv,
              float* __restrict__ Qo, float* __restrict__ Ko, float* __restrict__ Vo) {
    __shared__ GemmSmem sm;
    const float *A, *W, *bias; float* C;
    if (blockIdx.z == 0)      { A = q; W = Wq; bias = bq; C = Qo; }
    else if (blockIdx.z == 1) { A = k; W = Wk; bias = bk; C = Ko; }
    else                      { A = v; W = Wv; bias = bv; C = Vo; }
    gemm_body(A, W, bias, C, Bc * Sc, Dc, Dc, sm);
}

// ============================================================================
// Fused attention (round-4 proven config): 512 threads (16 warps, 8m x 2n).
// Q in registers, K/V cp.async double-buffered, E regs->gmem unnormalized,
// PV via shuffle transpose of S accumulators, inv written to gmem for norm_k.
// ============================================================================
#define FK0 0
#define FK1 8704
#define FV0 17408
#define FV1 26112
#define FRED 34816          // 256 floats: [row][wn]
#define FRED2 35072         // 128 floats: inv per row
#define FTOT 35200          // *4 = 140800 bytes

__global__ __launch_bounds__(512)
void fused_attn(const float* __restrict__ Qp, const float* __restrict__ Kp,
                const float* __restrict__ Vp, float* __restrict__ attn,
                float* __restrict__ invg, float* __restrict__ ctx) {
    extern __shared__ float smf[];
    const uint32_t sbase = smem_u32(smf);

    const int bh = blockIdx.y, b = bh >> 4, h = bh & 15;
    const int row0 = blockIdx.x * 128;
    const float* Qh = Qp + (size_t)b * Sc * Dc + h * HDc;
    const float* Kh = Kp + (size_t)b * Sc * Dc + h * HDc;
    const float* Vh = Vp + (size_t)b * Sc * Dc + h * HDc;
    float* outp = attn + (size_t)bh * Sc * Sc;

    const int tid = threadIdx.x, lane = tid & 31, warp = tid >> 5;
    const int wm = warp >> 1, wn = warp & 1;   // 8m x 2n
    const int g = lane >> 2, c = lane & 3;

    const int ldr0 = tid >> 4;                 // rows 0..31 (+32 per i)
    const int ldc4 = (tid & 15) * 4;

    // ---- issue first K/V tile ----
    {
#pragma unroll
        for (int i = 0; i < 4; i++) {
            int r = ldr0 + i * 32;
            cpa16(sbase + (uint32_t)(FK0 + r * 68 + ldc4) * 4, Kh + (size_t)r * Dc + ldc4);
            cpa16(sbase + (uint32_t)(FV0 + r * 68 + ldc4) * 4, Vh + (size_t)r * Dc + ldc4);
        }
        cpa_commit();
    }

    // ---- Q fragments in registers ----
    uint32_t qf[8][4];
    {
        const int qr = row0 + wm * 16;
#pragma unroll
        for (int s8 = 0; s8 < 8; s8++) {
            qf[s8][0] = f2tf(Qh[(size_t)(qr + g)     * Dc + s8 * 8 + c]);
            qf[s8][1] = f2tf(Qh[(size_t)(qr + g + 8) * Dc + s8 * 8 + c]);
            qf[s8][2] = f2tf(Qh[(size_t)(qr + g)     * Dc + s8 * 8 + c + 4]);
            qf[s8][3] = f2tf(Qh[(size_t)(qr + g + 8) * Dc + s8 * 8 + c + 4]);
        }
    }

    cpa_wait0();
    __syncthreads();

    float accU[8][4] = {};
    float rs0 = 0.f, rs1 = 0.f;

    const int src1 = (lane & ~3) | (c >> 1);
    const int src2 = src1 + 2;
    const bool odd = (c & 1);

    for (int kt = 0; kt < 16; kt++) {
        const int s = kt & 1;
        if (kt + 1 < 16) {
            const float* gk = Kh + (size_t)((kt + 1) * 128) * Dc;
            const float* gv = Vh + (size_t)((kt + 1) * 128) * Dc;
            const int KD = s ? FK0 : FK1;
            const int VD = s ? FV0 : FV1;
#pragma unroll
            for (int i = 0; i < 4; i++) {
                int r = ldr0 + i * 32;
                cpa16(sbase + (uint32_t)(KD + r * 68 + ldc4) * 4, gk + (size_t)r * Dc + ldc4);
                cpa16(sbase + (uint32_t)(VD + r * 68 + ldc4) * 4, gv + (size_t)r * Dc + ldc4);
            }
            cpa_commit();
        }
        const float* sK = smf + (s ? FK1 : FK0);
        const float* sV = smf + (s ? FV1 : FV0);
        const int k0 = kt * 128;

#pragma unroll
        for (int half = 0; half < 2; half++) {
            const int colbase = wn * 64 + half * 32;

            float accS[4][4] = {};
#pragma unroll
            for (int s8 = 0; s8 < 8; s8++) {
                uint32_t bf[4][2];
#pragma unroll
                for (int nt = 0; nt < 4; nt++) {
                    int kc = colbase + nt * 8 + g;
                    bf[nt][0] = __float_as_uint(sK[kc * 68 + s8 * 8 + c]);
                    bf[nt][1] = __float_as_uint(sK[kc * 68 + s8 * 8 + c + 4]);
                }
#pragma unroll
                for (int nt = 0; nt < 4; nt++)
                    mma8(accS[nt], qf[s8], bf[nt]);
            }

            const int grow = row0 + wm * 16 + g;
#pragma unroll
            for (int nt = 0; nt < 4; nt++) {
                float e0 = ex2(accS[nt][0] * KLOG2);
                float e1 = ex2(accS[nt][1] * KLOG2);
                float e2 = ex2(accS[nt][2] * KLOG2);
                float e3 = ex2(accS[nt][3] * KLOG2);
                rs0 += e0 + e1; rs1 += e2 + e3;
                int gcol = k0 + colbase + nt * 8 + c * 2;
                *reinterpret_cast<float2*>(&outp[(size_t)grow * Sc + gcol])       = make_float2(e0, e1);
                *reinterpret_cast<float2*>(&outp[(size_t)(grow + 8) * Sc + gcol]) = make_float2(e2, e3);
                accS[nt][0] = e0; accS[nt][1] = e1; accS[nt][2] = e2; accS[nt][3] = e3;
            }

#pragma unroll
            for (int s4 = 0; s4 < 4; s4++) {
                float x0 = __shfl_sync(0xffffffffu, accS[s4][0], src1);
                float x1 = __shfl_sync(0xffffffffu, accS[s4][1], src1);
                float y0 = __shfl_sync(0xffffffffu, accS[s4][2], src1);
                float y1 = __shfl_sync(0xffffffffu, accS[s4][3], src1);
                float z0 = __shfl_sync(0xffffffffu, accS[s4][0], src2);
                float z1 = __shfl_sync(0xffffffffu, accS[s4][1], src2);
                float w0 = __shfl_sync(0xffffffffu, accS[s4][2], src2);
                float w1 = __shfl_sync(0xffffffffu, accS[s4][3], src2);
                uint32_t af[4];
                af[0] = f2tf(odd ? x1 : x0);
                af[1] = f2tf(odd ? y1 : y0);
                af[2] = f2tf(odd ? z1 : z0);
                af[3] = f2tf(odd ? w1 : w0);
                const int vr = colbase + s4 * 8 + c;
#pragma unroll
                for (int nt = 0; nt < 8; nt++) {
                    uint32_t bf[2];
                    bf[0] = __float_as_uint(sV[vr * 68 + nt * 8 + g]);
                    bf[1] = __float_as_uint(sV[(vr + 4) * 68 + nt * 8 + g]);
                    mma8(accU[nt], af, bf);
                }
            }
        }

        if (kt + 1 < 16) cpa_wait0();
        __syncthreads();
    }

    // ---- rowsum reduction -> inv ----
    float* red  = smf + FRED;
    float* red2 = smf + FRED2;
    {
        float v0 = rs0, v1 = rs1;
        v0 += __shfl_xor_sync(0xffffffffu, v0, 1);
        v0 += __shfl_xor_sync(0xffffffffu, v0, 2);
        v1 += __shfl_xor_sync(0xffffffffu, v1, 1);
        v1 += __shfl_xor_sync(0xffffffffu, v1, 2);
        if (c == 0) {
            red[(wm * 16 + g) * 2 + wn]     = v0;
            red[(wm * 16 + g + 8) * 2 + wn] = v1;
        }
    }
    __syncthreads();
    if (tid < 128) {
        float iv = 1.0f / (red[tid * 2] + red[tid * 2 + 1]);
        invg[(size_t)bh * Sc + row0 + tid] = iv;
        red2[tid] = iv;
    }
    __syncthreads();

    // ---- cross-warp U reduction (wn=1 -> smem, wn=0 adds + writes ctx) ----
    float* uRed = smf;   // reuse K0 region, stride 68
    if (wn == 1) {
#pragma unroll
        for (int nt = 0; nt < 8; nt++) {
            int rr = wm * 16 + g, cc = nt * 8 + c * 2;
            uRed[rr * 68 + cc]           = accU[nt][0];
            uRed[rr * 68 + cc + 1]       = accU[nt][1];
            uRed[(rr + 8) * 68 + cc]     = accU[nt][2];
            uRed[(rr + 8) * 68 + cc + 1] = accU[nt][3];
        }
    }
    __syncthreads();
    if (wn == 0) {
        float* cp = ctx + (size_t)(b * Sc + row0) * Dc + h * HDc;
        int rr = wm * 16 + g;
        float iv0 = red2[rr], iv1 = red2[rr + 8];
#pragma unroll
        for (int nt = 0; nt < 8; nt++) {
            int cc = nt * 8 + c * 2;
            float u0 = accU[nt][0] + uRed[rr * 68 + cc];
            float u1 = accU[nt][1] + uRed[rr * 68 + cc + 1];
            float u2 = accU[nt][2] + uRed[(rr + 8) * 68 + cc];
            float u3 = accU[nt][3] + uRed[(rr + 8) * 68 + cc + 1];
            cp[(size_t)rr * Dc + cc]           = u0 * iv0;
            cp[(size_t)rr * Dc + cc + 1]       = u1 * iv0;
            cp[(size_t)(rr + 8) * Dc + cc]     = u2 * iv1;
            cp[(size_t)(rr + 8) * Dc + cc + 1] = u3 * iv1;
        }
    }
}

// ============================================================================
// normalize attn in place: attn[row, :] *= inv[row]   (pure bandwidth)
// ============================================================================
__global__ void norm_k(float4* __restrict__ attn4, const float* __restrict__ inv) {
    const size_t total = (size_t)BHc * Sc * Sc / 4;
    size_t i = (size_t)blockIdx.x * blockDim.x + threadIdx.x;
    const size_t stride = (size_t)gridDim.x * blockDim.x;
    for (; i < total; i += stride) {
        float s = __ldg(&inv[i >> 9]);     // 512 float4 per row
        float4 v = attn4[i];
        v.x *= s; v.y *= s; v.z *= s; v.w *= s;
        attn4[i] = v;
    }
}

// ---------------------------------------------------------------------------
extern "C" void kernel_launch(void* const* d_in, const int* in_sizes, int n_in,
                              void* d_out, int out_size) {
    const float* query = (const float*)d_in[0];
    const float* key   = (const float*)d_in[1];
    const float* value = (const float*)d_in[2];
    const float* Wq = (const float*)d_in[3];
    const float* bq = (const float*)d_in[4];
    const float* Wk = (const float*)d_in[5];
    const float* bk = (const float*)d_in[6];
    const float* Wv = (const float*)d_in[7];
    const float* bv = (const float*)d_in[8];
    const float* Wo = (const float*)d_in[9];
    const float* bo = (const float*)d_in[10];

    float* out = (float*)d_out;
    const size_t OUT_E  = (size_t)Bc * Sc * Dc;
    const size_t ATTN_E = (size_t)BHc * Sc * Sc;

    float* attn;
    if ((size_t)out_size >= OUT_E + ATTN_E) {
        attn = out + OUT_E;
    } else {
        void* p = nullptr; cudaGetSymbolAddress(&p, g_attn_fb); attn = (float*)p;
    }
    float* Qp;   { void* p; cudaGetSymbolAddress(&p, g_Q);      Qp = (float*)p; }
    float* Kp;   { void* p; cudaGetSymbolAddress(&p, g_K);      Kp = (float*)p; }
    float* Vp;   { void* p; cudaGetSymbolAddress(&p, g_V);      Vp = (float*)p; }
    float* Cx;   { void* p; cudaGetSymbolAddress(&p, g_ctx);    Cx = (float*)p; }
    float* isum; { void* p; cudaGetSymbolAddress(&p, g_invsum); isum = (float*)p; }

    cudaFuncSetAttribute(fused_attn, cudaFuncAttributeMaxDynamicSharedMemorySize,
                         FTOT * 4);

    const int M = Bc * Sc;                      // 4096
    dim3 thr(256);

    qkv_gemm<<<dim3(Dc / 128, M / 128, 3), thr>>>(query, key, value,
                                                  Wq, bq, Wk, bk, Wv, bv,
                                                  Qp, Kp, Vp);

    dim3 gfa(Sc / 128, BHc);                    // (16, 32)
    fused_attn<<<gfa, dim3(512), FTOT * 4>>>(Qp, Kp, Vp, attn, isum, Cx);

    norm_k<<<4736, 256>>>((float4*)attn, isum);

    gemm_bias_tc<<<dim3(Dc / 128, M / 128), thr>>>(Cx, Wo, bo, out, M, Dc, Dc);
}